// round 17
// baseline (speedup 1.0000x reference)
#include <cuda_runtime.h>
#include <cuda_bf16.h>
#include <math.h>

#define NG 9
#define BMAXE 8192
#define ITILE 1024          // i's per tile = TPB2 * RPT
#define RPT 4               // i's per thread
#define TPB2 256
#define G2 444              // grid: 148 SMs x 3 co-resident blocks
#define SLICEBLKS 256       // blocks that own a 32-element input slice
#define CHUNKMAX 128        // j's staged in shared per round
#define LOG2E 1.4426950408889634f
#define LN2   0.6931471805599453f

// packed f32x2 FMA: acc += a * b (two lanes)
#define FFMA2(acc, a, bb) asm("fma.rn.f32x2 %0, %1, %2, %0;" : "+l"(acc) : "l"(a), "l"(bb))

// ---------------- device globals (scratch; zero-init once; reset in-kernel) ----------------
__device__ __align__(16) float    d_lp[BMAXE + ITILE];
__device__ __align__(16) unsigned d_mp[BMAXE + ITILE];
__device__ __align__(16) float    d_ln[BMAXE];
__device__ __align__(16) unsigned d_mn[BMAXE];
__device__ int d_blkTox[SLICEBLKS];
__device__ int d_cntSP[NG], d_cntSN[NG];
__device__ __align__(16) float d_partial[27 * G2];   // TRANSPOSED: [lane][block]
__device__ int d_barCnt[3];                          // grid barrier counters (reset by block 0)
__device__ int d_barFlag[3];

// grid-wide barrier: all G2 blocks co-resident (3/SM guaranteed by launch_bounds), deterministic
__device__ __forceinline__ void gridBarrier(int id) {
    __syncthreads();
    if (threadIdx.x == 0) {
        __threadfence();
        volatile int* flag = &d_barFlag[id];
        if (atomicAdd(&d_barCnt[id], 1) == G2 - 1) {
            *flag = 1;
        } else {
            while (*flag == 0) { }
        }
        __threadfence();
    }
    __syncthreads();
}

__global__ void __launch_bounds__(TPB2, 3)
fused_kernel(const float* __restrict__ logits,
             const float* __restrict__ ytox,
             const float* __restrict__ yid,
             float* __restrict__ out, int B) {
    const int b    = blockIdx.x;
    const int t    = threadIdx.x;
    const int lane = t & 31;
    const int wid  = t >> 5;

    // ---- shared ----
    __shared__ int   sTox[SLICEBLKS];
    __shared__ int   sW[8], sP[8], sBc[2];
    __shared__ float  sLj[CHUNKMAX];
    __shared__ float2 sM[CHUNKMAX][6];
    __shared__ float  sPart[TPB2 * 29];
    __shared__ float  sQ[27][8];
    __shared__ float  accF[27];

    // ================= Phase A: masks + tox + counts (warp 0 of blocks < 256) =================
    float    myLg = 0.0f;
    unsigned myMask = 0u;
    int      myTox = 0, myValid = 0;
    unsigned balTox = 0u;
    if (b < SLICEBLKS && wid == 0) {
        int i = b * 32 + lane;
        if (i < B) {
            myValid = 1;
            myLg  = logits[i];
            myTox = (ytox[i] >= 0.5f) ? 1 : 0;
            const float* row = yid + (size_t)i * NG;
            #pragma unroll
            for (int g = 0; g < NG; g++)
                if (row[g] >= 0.5f) myMask |= (1u << g);
        }
        balTox = __ballot_sync(0xFFFFFFFFu, myTox);
        unsigned bgAll[NG];
        #pragma unroll
        for (int g = 0; g < NG; g++)
            bgAll[g] = __ballot_sync(0xFFFFFFFFu, (myMask >> g) & 1u);
        int myCnt = 0;
        #pragma unroll
        for (int g = 0; g < NG; g++) {
            if (lane == g)      myCnt = __popc(bgAll[g] & balTox);    // SP
            if (lane == NG + g) myCnt = __popc(bgAll[g] & ~balTox);   // SN
        }
        if (lane < NG)            atomicAdd(&d_cntSP[lane], myCnt);
        else if (lane < 2 * NG)   atomicAdd(&d_cntSN[lane - NG], myCnt);
        if (lane == 0) d_blkTox[b] = __popc(balTox);
    }
    gridBarrier(0);

    // ================= Phase B: prefix + scatter + pad =================
    if (t < SLICEBLKS) sTox[t] = d_blkTox[t];
    __syncthreads();
    {
        int x   = (t < SLICEBLKS) ? sTox[t] : 0;
        int pre = (t < b) ? x : 0;                  // toxic count in blocks before mine
        #pragma unroll
        for (int o = 16; o > 0; o >>= 1) {
            x   += __shfl_xor_sync(0xFFFFFFFFu, x, o);
            pre += __shfl_xor_sync(0xFFFFFFFFu, pre, o);
        }
        if (lane == 0) { sW[wid] = x; sP[wid] = pre; }
    }
    __syncthreads();
    if (t == 0) {
        int X = 0, P = 0;
        #pragma unroll
        for (int w = 0; w < 8; w++) { X += sW[w]; P += sP[w]; }
        sBc[0] = X; sBc[1] = P;
    }
    __syncthreads();
    const int nP    = sBc[0];
    const int myPre = sBc[1];
    const int nN    = B - nP;

    if (b < SLICEBLKS && wid == 0 && myValid) {
        int toxBefore = __popc(balTox & ((1u << lane) - 1u));
        int i = b * 32 + lane;
        if (myTox) {
            int p = myPre + toxBefore;
            d_lp[p] = myLg; d_mp[p] = myMask;
        } else {
            int p = i - myPre - toxBefore;
            d_ln[p] = myLg; d_mn[p] = myMask;
        }
    }
    int nTileI = (nP + ITILE - 1) / ITILE; if (nTileI < 1) nTileI = 1;
    const int nPpad = nTileI * ITILE;
    {
        int k = b * TPB2 + t;
        if (k < nPpad - nP) { d_lp[nP + k] = 1e30f; d_mp[nP + k] = 0u; }  // sentinel: s == 0
    }
    gridBarrier(1);

    // ================= Phase C: pair accumulation =================
    int it  = b % nTileI;
    int idx = b / nTileI;
    int nB  = (G2 + nTileI - 1 - it) / nTileI;
    int j0  = (int)((long long)idx * nN / nB);
    int j1  = (int)((long long)(idx + 1) * nN / nB);
    if (j0 > j1) j1 = j0;

    float li2[RPT]; unsigned mi[RPT];
    int ib = it * ITILE + t;
    #pragma unroll
    for (int r = 0; r < RPT; r++) {
        li2[r] = d_lp[ib + r * TPB2] * LOG2E;
        mi[r]  = d_mp[ib + r * TPB2];
    }

    unsigned long long H2[RPT][5];   // packed f32x2: groups (0,1)(2,3)(4,5)(6,7)(8,rowsum)
    #pragma unroll
    for (int r = 0; r < RPT; r++)
        #pragma unroll
        for (int g = 0; g < 5; g++) H2[r][g] = 0ull;

    for (int jc = j0; jc < j1; jc += CHUNKMAX) {
        int jcnt = j1 - jc; if (jcnt > CHUNKMAX) jcnt = CHUNKMAX;
        __syncthreads();
        for (int j = t; j < jcnt; j += TPB2) {
            sLj[j] = d_ln[jc + j] * LOG2E;
            unsigned m = d_mn[jc + j];
            #pragma unroll
            for (int g = 0; g < 5; g++) {
                float x = (float)((m >> (2 * g)) & 1u);
                float y = (g < 4) ? (float)((m >> (2 * g + 1)) & 1u) : 1.0f;  // lane 9 = rowsum
                sM[j][g] = make_float2(x, y);
            }
        }
        __syncthreads();

        for (int j = 0; j < jcnt; j++) {
            const float lj2 = sLj[j];
            const unsigned long long* qp = (const unsigned long long*)&sM[j][0];
            const unsigned long long q0 = qp[0], q1 = qp[1], q2 = qp[2], q3 = qp[3], q4 = qp[4];
            #pragma unroll
            for (int r = 0; r < RPT; r++) {
                // softplus in log2 domain: s2 = lg2(1 + 2^(lj2-li2)); s = s2*ln2 applied at end
                float d2 = lj2 - li2[r];
                float e;  asm("ex2.approx.ftz.f32 %0, %1;" : "=f"(e) : "f"(d2));
                float u = 1.0f + e;
                float s2; asm("lg2.approx.ftz.f32 %0, %1;" : "=f"(s2) : "f"(u));
                unsigned long long sp;
                asm("mov.b64 %0, {%1, %1};" : "=l"(sp) : "r"(__float_as_uint(s2)));
                FFMA2(H2[r][0], sp, q0);
                FFMA2(H2[r][1], sp, q1);
                FFMA2(H2[r][2], sp, q2);
                FFMA2(H2[r][3], sp, q3);
                FFMA2(H2[r][4], sp, q4);   // .y accumulates rowsum (Gr)
            }
        }
    }

    // per-thread partials: both / jin / iin (log2 units)
    {
        float p[27];
        #pragma unroll
        for (int k = 0; k < 27; k++) p[k] = 0.0f;
        #pragma unroll
        for (int r = 0; r < RPT; r++) {
            float Hf[10];
            #pragma unroll
            for (int g = 0; g < 5; g++) {
                uint2 u = *(uint2*)&H2[r][g];
                Hf[2 * g]     = __uint_as_float(u.x);
                Hf[2 * g + 1] = __uint_as_float(u.y);
            }
            float Gr = Hf[9];
            #pragma unroll
            for (int g = 0; g < NG; g++) {
                p[NG + g] += Hf[g];
                if ((mi[r] >> g) & 1u) { p[g] += Hf[g]; p[2 * NG + g] += Gr; }
            }
        }
        #pragma unroll
        for (int k = 0; k < 27; k++) sPart[t * 29 + k] = p[k];
    }
    __syncthreads();

    if (t < 216) {
        int k  = t >> 3;
        int p8 = t & 7;
        float s = 0.0f;
        #pragma unroll
        for (int m = 0; m < 32; m++) {
            int mm = (m + 4 * p8) & 31;
            s += sPart[(p8 * 32 + mm) * 29 + k];
        }
        sQ[k][p8] = s;
    }
    __syncthreads();
    if (t < 27) {
        float v = 0.0f;
        #pragma unroll
        for (int p = 0; p < 8; p++) v += sQ[t][p];
        d_partial[t * G2 + b] = v;
    }

    // ================= finalize: block 0, fixed order =================
    gridBarrier(2);
    if (b == 0) {
        for (int k = wid; k < 27; k += 8) {
            float s = 0.0f;
            for (int bb = lane; bb < G2; bb += 32) s += d_partial[k * G2 + bb];
            #pragma unroll
            for (int o = 16; o > 0; o >>= 1) s += __shfl_xor_sync(0xFFFFFFFFu, s, o);
            if (lane == 0) accF[k] = s * LN2;   // log2 -> nat units
        }
        __syncthreads();
        if (t == 0) {
            float fnP = (float)nP, fnN = (float)nN;
            float sum4 = 0.0f, sgv = 0.0f;
            #pragma unroll
            for (int g = 0; g < NG; g++) {
                float SP = (float)d_cntSP[g], SN = (float)d_cntSN[g];
                float BP = fnP - SP, BN = fnN - SN;
                float both = accF[g], jin = accF[NG + g], iin = accF[2 * NG + g];
                float num0 = both, num1 = jin - both, num2 = iin - both;
                float cnt0 = SP * SN, cnt1 = BP * SN, cnt2 = SP * BN;   // exact in fp32
                float nv = 0.0f, accl = 0.0f;
                if (cnt0 > 0.0f) { nv += 1.0f; accl += num0 / fmaxf(cnt0, 1.0f); }
                if (cnt1 > 0.0f) { nv += 1.0f; accl += num1 / fmaxf(cnt1, 1.0f); }
                if (cnt2 > 0.0f) { nv += 1.0f; accl += num2 / fmaxf(cnt2, 1.0f); }
                float gl = accl / fmaxf(nv, 1.0f);
                float gv = (nv > 0.0f) ? 1.0f : 0.0f;
                sgv += gv;
                float gl2 = gl * gl;
                sum4 += gl2 * gl2 * gv;
            }
            float meanp = sum4 / fmaxf(sgv, 1.0f);
            float loss  = sqrtf(sqrtf(meanp));
            out[0] = (sgv > 0.0f) ? loss : 0.0f;
            // reset all cross-replay state (graph replays must be identical)
            #pragma unroll
            for (int g = 0; g < NG; g++) { d_cntSP[g] = 0; d_cntSN[g] = 0; }
            d_barCnt[0] = 0; d_barCnt[1] = 0; d_barCnt[2] = 0;
            d_barFlag[0] = 0; d_barFlag[1] = 0; d_barFlag[2] = 0;
            __threadfence();
        }
    }
}

// ---------------- launch ----------------
extern "C" void kernel_launch(void* const* d_in, const int* in_sizes, int n_in,
                              void* d_out, int out_size) {
    const float* logits = (const float*)d_in[0];
    const float* ytox   = (const float*)d_in[1];
    const float* yid    = (const float*)d_in[2];
    int B = in_sizes[0];
    if (B > BMAXE) B = BMAXE;

    fused_kernel<<<G2, TPB2>>>(logits, ytox, yid, (float*)d_out, B);
}